// round 1
// baseline (speedup 1.0000x reference)
#include <cuda_runtime.h>
#include <cstdint>

// ---------------------------------------------------------------------------
// Algebraic collapse of the whole network:
//   out[b] = sum_{n,p} (Agg_b^2)[n,p] * (x_b[p] . t_n)
//          + sum_n rowsum(Agg_b)[n] * s_n  +  c1
// where t_n (4x14), s_n (4), c1 (1) are precomputed from the weights:
//   M  = Wl1 (Wl2 (Wl3 wl4) + wl4) + wl4                 (256)
//   c0 = ((bl1 Wl2 + bl2) Wl3 + bl3 + bl1) . wl4 + bl4
//   v_n = W2 @ M[64n:64n+64]   (128)
//   t_n = W1 @ v_n             (14)
//   s_n = b1 . v_n
//   c1  = c0 + sum_n b2 . M[64n:64n+64]
// ---------------------------------------------------------------------------

__device__ float g_p1[256];   // Wl3 @ wl4
__device__ float g_zc1[256];  // bl1 @ Wl2 + bl2
__device__ float g_r[256];    // Wl2 @ p1 + wl4
__device__ float g_zc[256];   // zc1 @ Wl3 + bl3 + bl1
__device__ float g_TSC[61];   // T[56], s[4], c1

// ---- precompute kernel 1: p1 (row pattern on Wl3), zc1 (col pattern on Wl2)
__global__ void pre1(const float* __restrict__ Wl2, const float* __restrict__ bl1,
                     const float* __restrict__ bl2, const float* __restrict__ Wl3,
                     const float* __restrict__ wl4)
{
    __shared__ float sv[256];
    int tid = threadIdx.x;                 // 128 threads
    int part = blockIdx.x >> 1;            // 0: p1, 1: zc1
    int j = (blockIdx.x & 1) * 128 + tid;
    if (part == 0) {
        sv[tid] = wl4[tid]; sv[tid + 128] = wl4[tid + 128];
        __syncthreads();
        const float4* row = (const float4*)(Wl3 + (size_t)j * 256);
        const float4* v4  = (const float4*)sv;
        float acc = 0.f;
        #pragma unroll 8
        for (int k = 0; k < 64; k++) {
            float4 a = row[k], b = v4[k];
            acc += a.x * b.x + a.y * b.y + a.z * b.z + a.w * b.w;
        }
        g_p1[j] = acc;
    } else {
        sv[tid] = bl1[tid]; sv[tid + 128] = bl1[tid + 128];
        __syncthreads();
        float acc = bl2[j];
        #pragma unroll 8
        for (int i = 0; i < 256; i++) acc += sv[i] * Wl2[(size_t)i * 256 + j];
        g_zc1[j] = acc;
    }
}

// ---- precompute kernel 2: r (row pattern on Wl2), zc (col pattern on Wl3)
__global__ void pre2(const float* __restrict__ Wl2, const float* __restrict__ Wl3,
                     const float* __restrict__ bl1, const float* __restrict__ bl3,
                     const float* __restrict__ wl4)
{
    __shared__ float sv[256];
    int tid = threadIdx.x;
    int part = blockIdx.x >> 1;
    int j = (blockIdx.x & 1) * 128 + tid;
    if (part == 0) {
        sv[tid] = g_p1[tid]; sv[tid + 128] = g_p1[tid + 128];
        __syncthreads();
        const float4* row = (const float4*)(Wl2 + (size_t)j * 256);
        const float4* v4  = (const float4*)sv;
        float acc = 0.f;
        #pragma unroll 8
        for (int k = 0; k < 64; k++) {
            float4 a = row[k], b = v4[k];
            acc += a.x * b.x + a.y * b.y + a.z * b.z + a.w * b.w;
        }
        g_r[j] = acc + wl4[j];
    } else {
        sv[tid] = g_zc1[tid]; sv[tid + 128] = g_zc1[tid + 128];
        __syncthreads();
        float acc = bl3[j] + bl1[j];
        #pragma unroll 8
        for (int i = 0; i < 256; i++) acc += sv[i] * Wl3[(size_t)i * 256 + j];
        g_zc[j] = acc;
    }
}

// ---- precompute kernel 3 (single block): M, c0, V, then T/s/c1
__global__ void pre3(const float* __restrict__ Wl1, const float* __restrict__ wl4,
                     const float* __restrict__ bl4, const float* __restrict__ W2,
                     const float* __restrict__ W1,  const float* __restrict__ b1,
                     const float* __restrict__ b2)
{
    __shared__ float sr[256];
    __shared__ float sM[256];
    __shared__ float sV[512];
    __shared__ float red[256];
    __shared__ float sc0;
    int tid = threadIdx.x;  // 256 threads
    sr[tid] = g_r[tid];
    red[tid] = g_zc[tid] * wl4[tid];
    __syncthreads();
    // M[tid] = row_tid(Wl1) . r + wl4[tid]
    {
        const float4* row = (const float4*)(Wl1 + (size_t)tid * 256);
        const float4* v4  = (const float4*)sr;
        float acc = 0.f;
        #pragma unroll 8
        for (int k = 0; k < 64; k++) {
            float4 a = row[k], b = v4[k];
            acc += a.x * b.x + a.y * b.y + a.z * b.z + a.w * b.w;
        }
        sM[tid] = acc + wl4[tid];
    }
    // c0 reduction
    for (int off = 128; off > 0; off >>= 1) {
        if (tid < off) red[tid] += red[tid + off];
        __syncthreads();
    }
    if (tid == 0) sc0 = red[0] + bl4[0];
    __syncthreads();
    // V[n*128+k] = sum_j W2[k,j] * M[n*64+j]   (512 outputs, 2 per thread)
    #pragma unroll
    for (int rep = 0; rep < 2; rep++) {
        int o = tid + rep * 256;
        int n = o >> 7, k = o & 127;
        float a = 0.f;
        #pragma unroll 8
        for (int j = 0; j < 64; j++) a += W2[k * 64 + j] * sM[n * 64 + j];
        sV[o] = a;
    }
    __syncthreads();
    if (tid < 56) {
        int n = tid / 14, i = tid % 14;
        float a = 0.f;
        #pragma unroll 8
        for (int k = 0; k < 128; k++) a += W1[i * 128 + k] * sV[n * 128 + k];
        g_TSC[tid] = a;
    } else if (tid < 60) {
        int n = tid - 56;
        float a = 0.f;
        #pragma unroll 8
        for (int k = 0; k < 128; k++) a += b1[k] * sV[n * 128 + k];
        g_TSC[tid] = a;
    } else if (tid == 60) {
        float a = sc0;
        #pragma unroll
        for (int n = 0; n < 4; n++)
            for (int j = 0; j < 64; j++) a += b2[j] * sM[n * 64 + j];
        g_TSC[60] = a;
    }
}

// ---- main kernel: one thread per sample, fully register-resident graph math
__global__ __launch_bounds__(256)
void gcn_main(const float* __restrict__ x, const int* __restrict__ eidx,
              float* __restrict__ out, int B)
{
    __shared__ float sT[64];
    if (threadIdx.x < 61) sT[threadIdx.x] = g_TSC[threadIdx.x];
    __syncthreads();
    int b = blockIdx.x * 256 + threadIdx.x;
    if (b >= B) return;

    // edges: [B, 2, 12] int32 -> 6 int4 loads (96B, fully consumed)
    const int4* E = (const int4*)eidx + (size_t)b * 6;
    int4 e0 = E[0], e1 = E[1], e2 = E[2], e3 = E[3], e4 = E[4], e5 = E[5];
    // x: [B, 4, 14] f32 -> 14 float4 loads (224B, 16B-aligned, fully consumed)
    const float4* X = (const float4*)x + (size_t)b * 14;
    float4 xv[14];
    #pragma unroll
    for (int i = 0; i < 14; i++) xv[i] = X[i];

    int es[12] = {e0.x,e0.y,e0.z,e0.w, e1.x,e1.y,e1.z,e1.w, e2.x,e2.y,e2.z,e2.w};
    int ed[12] = {e3.x,e3.y,e3.z,e3.w, e4.x,e4.y,e4.z,e4.w, e5.x,e5.y,e5.z,e5.w};

    // nibble-packed 16-bin histogram of codes (dst*4+src); self loops pre-added
    unsigned h0 = 1u + (1u << 20);        // codes 0 (0,0) and 5 (1,1)
    unsigned h1 = (1u << 8) + (1u << 28); // codes 10 (2,2) and 15 (3,3)
    #pragma unroll
    for (int e = 0; e < 12; e++) {
        int code = (ed[e] << 2) | es[e];
        unsigned inc = 1u << ((code & 7) << 2);
        if (code & 8) h1 += inc; else h0 += inc;
    }
    float c[16];
    #pragma unroll
    for (int q = 0; q < 8; q++) {
        c[q]     = (float)((h0 >> (q * 4)) & 15u);
        c[q + 8] = (float)((h1 >> (q * 4)) & 15u);
    }
    // deg[d] = row-sum of counts (dst occurrences incl. self loop), always >= 1
    float dinv[4];
    #pragma unroll
    for (int d = 0; d < 4; d++)
        dinv[d] = rsqrtf(c[4*d] + c[4*d+1] + c[4*d+2] + c[4*d+3]);
    // Agg[d][s] = count * dinv[d] * dinv[s]
    float A[16];
    #pragma unroll
    for (int d = 0; d < 4; d++)
        #pragma unroll
        for (int s = 0; s < 4; s++)
            A[d*4+s] = c[d*4+s] * dinv[d] * dinv[s];
    // A2 = Agg^2, R = row sums of Agg
    float A2[16], R[4];
    #pragma unroll
    for (int n = 0; n < 4; n++) {
        R[n] = A[n*4] + A[n*4+1] + A[n*4+2] + A[n*4+3];
        #pragma unroll
        for (int p = 0; p < 4; p++) {
            float a = A[n*4+0] * A[0*4+p];
            a += A[n*4+1] * A[1*4+p];
            a += A[n*4+2] * A[2*4+p];
            a += A[n*4+3] * A[3*4+p];
            A2[n*4+p] = a;
        }
    }
    // flatten x into scalar regs (static indices only -> stays in registers)
    float xf[56];
    #pragma unroll
    for (int i = 0; i < 14; i++) {
        xf[4*i+0] = xv[i].x; xf[4*i+1] = xv[i].y;
        xf[4*i+2] = xv[i].z; xf[4*i+3] = xv[i].w;
    }
    float acc = sT[60] + R[0]*sT[56] + R[1]*sT[57] + R[2]*sT[58] + R[3]*sT[59];
    #pragma unroll
    for (int n = 0; n < 4; n++) {
        #pragma unroll
        for (int i = 0; i < 14; i++) {
            float y = A2[n*4+0] * xf[i]      + A2[n*4+1] * xf[14+i]
                    + A2[n*4+2] * xf[28+i]   + A2[n*4+3] * xf[42+i];
            acc += sT[n*14+i] * y;
        }
    }
    out[b] = acc;
}

extern "C" void kernel_launch(void* const* d_in, const int* in_sizes, int n_in,
                              void* d_out, int out_size)
{
    const float* x   = (const float*)d_in[0];
    const int*   ei  = (const int*)  d_in[1];
    const float* W1  = (const float*)d_in[2];
    const float* b1  = (const float*)d_in[3];
    const float* W2  = (const float*)d_in[4];
    const float* b2  = (const float*)d_in[5];
    const float* Wl1 = (const float*)d_in[6];
    const float* bl1 = (const float*)d_in[7];
    const float* Wl2 = (const float*)d_in[8];
    const float* bl2 = (const float*)d_in[9];
    const float* Wl3 = (const float*)d_in[10];
    const float* bl3 = (const float*)d_in[11];
    const float* wl4 = (const float*)d_in[12];
    const float* bl4 = (const float*)d_in[13];

    int B = in_sizes[0] / 56;   // x is [B, 4, 14]

    pre1<<<4, 128>>>(Wl2, bl1, bl2, Wl3, wl4);
    pre2<<<4, 128>>>(Wl2, Wl3, bl1, bl3, wl4);
    pre3<<<1, 256>>>(Wl1, wl4, bl4, W2, W1, b1, b2);
    gcn_main<<<(B + 255) / 256, 256>>>(x, ei, (float*)d_out, B);
}

// round 3
// speedup vs baseline: 2.4165x; 2.4165x over previous
#include <cuda_runtime.h>
#include <cstdint>

// ---------------------------------------------------------------------------
// out[b] = sum_{n,p} (Agg_b^2)[n,p] * (x_b[p] . t_n)
//        + sum_n rowsum(Agg_b)[n] * s_n  +  c1
//
// Precompute (all row-pattern matvecs):
//   p1 = Wl3 . wl4
//   q  = Wl2 . p1 + wl4
//   M  = Wl1 . q  + wl4
//   c0 = bl1.q + bl2.p1 + bl3.wl4 + bl4     (bl1.q includes bl1.wl4 term)
//   v_n = W2 @ M_n ; t_n = W1 @ v_n ; s_n = b1.v_n ; c1 = c0 + sum_n b2.M_n
// ---------------------------------------------------------------------------

__device__ float g_p1[256];
__device__ float g_q[256];
__device__ float g_M[256];
__device__ float g_TSC[61];   // T[56], s[4], c1

// ---- warp-per-row 256x256 matvec; globals selected BY SYMBOL in device code
__global__ void matvec256(const float* __restrict__ W, const float* __restrict__ extv,
                          const float* __restrict__ addv, int stage)
{
    const float* v = (stage == 0) ? extv : (stage == 1 ? g_p1 : g_q);
    float* outv    = (stage == 0) ? g_p1 : (stage == 1 ? g_q  : g_M);
    int warp = threadIdx.x >> 5, lane = threadIdx.x & 31;
    int r = blockIdx.x * 8 + warp;
    const float* row = W + (size_t)r * 256;
    float a = 0.f;
    #pragma unroll
    for (int k = 0; k < 8; k++) a += row[lane + 32 * k] * v[lane + 32 * k];
    #pragma unroll
    for (int o = 16; o > 0; o >>= 1) a += __shfl_xor_sync(0xFFFFFFFFu, a, o);
    if (lane == 0) outv[r] = a + (addv ? addv[r] : 0.f);
}

// ---- finalize: V, T, s, c1 (reads g_p1/g_q/g_M by symbol)
__global__ void finalize(const float* __restrict__ W1, const float* __restrict__ b1,
                         const float* __restrict__ W2, const float* __restrict__ b2,
                         const float* __restrict__ bl1, const float* __restrict__ bl2,
                         const float* __restrict__ bl3, const float* __restrict__ wl4,
                         const float* __restrict__ bl4)
{
    __shared__ float sM[256];
    __shared__ float sV[512];
    __shared__ float red[256];
    int t = threadIdx.x;   // 256 threads
    float m = g_M[t];
    sM[t] = m;
    float contrib = bl1[t] * g_q[t] + bl2[t] * g_p1[t] + bl3[t] * wl4[t];
    __syncthreads();
    if (t < 64)
        contrib += b2[t] * (sM[t] + sM[64 + t] + sM[128 + t] + sM[192 + t]);
    red[t] = contrib;
    __syncthreads();
    for (int o = 128; o > 0; o >>= 1) {
        if (t < o) red[t] += red[t + o];
        __syncthreads();
    }
    // V[n*128+k] = W2[k,:] . M_n
    #pragma unroll
    for (int rep = 0; rep < 2; rep++) {
        int o = t + rep * 256;
        int n = o >> 7, k = o & 127;
        const float4* w4 = (const float4*)(W2 + (size_t)k * 64);
        const float4* m4 = (const float4*)(sM + n * 64);
        float a = 0.f;
        #pragma unroll
        for (int j = 0; j < 16; j++) {
            float4 w = w4[j], mm = m4[j];
            a += w.x * mm.x + w.y * mm.y + w.z * mm.z + w.w * mm.w;
        }
        sV[o] = a;
    }
    __syncthreads();
    if (t < 56) {
        int n = t / 14, i = t % 14;
        const float4* w4 = (const float4*)(W1 + (size_t)i * 128);
        const float4* v4 = (const float4*)(sV + n * 128);
        float a = 0.f;
        #pragma unroll
        for (int k = 0; k < 32; k++) {
            float4 w = w4[k], vv = v4[k];
            a += w.x * vv.x + w.y * vv.y + w.z * vv.z + w.w * vv.w;
        }
        g_TSC[t] = a;
    } else if (t < 60) {
        int n = t - 56;
        const float4* b4 = (const float4*)b1;
        const float4* v4 = (const float4*)(sV + n * 128);
        float a = 0.f;
        #pragma unroll
        for (int k = 0; k < 32; k++) {
            float4 w = b4[k], vv = v4[k];
            a += w.x * vv.x + w.y * vv.y + w.z * vv.z + w.w * vv.w;
        }
        g_TSC[t] = a;
    } else if (t == 60) {
        g_TSC[60] = red[0] + bl4[0];
    }
}

// ---- main kernel: 128 threads/block, static shared (no opt-in attribute)
#define TPB 128
#define XS 57
#define ES 25

__global__ __launch_bounds__(TPB)
void gcn_main(const float* __restrict__ x, const int* __restrict__ eidx,
              float* __restrict__ out)
{
    __shared__ float sx[TPB * XS];
    __shared__ int   se[TPB * ES];
    __shared__ float sT[64];
    int tid = threadIdx.x;

    // ---- stage: fully coalesced global -> shared (all 20 loads in flight)
    const float4* Xg = (const float4*)x + (size_t)blockIdx.x * TPB * 14;
    const int4*   Eg = (const int4*)eidx + (size_t)blockIdx.x * TPB * 6;
    float4 xv[14];
    int4   ev[6];
    #pragma unroll
    for (int i = 0; i < 14; i++) xv[i] = Xg[i * TPB + tid];
    #pragma unroll
    for (int i = 0; i < 6; i++)  ev[i] = Eg[i * TPB + tid];
    if (tid < 61) sT[tid] = g_TSC[tid];
    #pragma unroll
    for (int i = 0; i < 14; i++) {
        int idx4 = i * TPB + tid;          // float4 index in block tile
        int s = idx4 / 14, j = idx4 % 14;  // sample, float4-within-sample
        float* dst = sx + s * XS + j * 4;
        dst[0] = xv[i].x; dst[1] = xv[i].y; dst[2] = xv[i].z; dst[3] = xv[i].w;
    }
    #pragma unroll
    for (int i = 0; i < 6; i++) {
        int i4 = i * TPB + tid;
        int s = i4 / 6, r = i4 % 6;
        int* dst = se + s * ES + r * 4;
        dst[0] = ev[i].x; dst[1] = ev[i].y; dst[2] = ev[i].z; dst[3] = ev[i].w;
    }
    __syncthreads();

    // ---- per-sample graph math (odd LDS strides -> conflict-free)
    const int* me = se + tid * ES;
    unsigned h0 = 1u + (1u << 20);         // self loops: codes 0, 5
    unsigned h1 = (1u << 8) + (1u << 28);  // codes 10, 15
    #pragma unroll
    for (int e = 0; e < 12; e++) {
        int code = (me[12 + e] << 2) | me[e];   // dst*4 + src
        unsigned inc = 1u << ((code & 7) << 2);
        if (code & 8) h1 += inc; else h0 += inc;
    }
    float c[16];
    #pragma unroll
    for (int qd = 0; qd < 8; qd++) {
        c[qd]     = (float)((h0 >> (qd * 4)) & 15u);
        c[qd + 8] = (float)((h1 >> (qd * 4)) & 15u);
    }
    float dinv[4];
    #pragma unroll
    for (int d = 0; d < 4; d++)
        dinv[d] = rsqrtf(c[4*d] + c[4*d+1] + c[4*d+2] + c[4*d+3]);
    float A[16];
    #pragma unroll
    for (int d = 0; d < 4; d++)
        #pragma unroll
        for (int s = 0; s < 4; s++)
            A[d*4+s] = c[d*4+s] * dinv[d] * dinv[s];
    float A2[16], R[4];
    #pragma unroll
    for (int n = 0; n < 4; n++) {
        R[n] = A[n*4] + A[n*4+1] + A[n*4+2] + A[n*4+3];
        #pragma unroll
        for (int p = 0; p < 4; p++) {
            A2[n*4+p] = A[n*4+0] * A[0*4+p] + A[n*4+1] * A[1*4+p]
                      + A[n*4+2] * A[2*4+p] + A[n*4+3] * A[3*4+p];
        }
    }

    // d[p*4+n] = x_p . t_n   (f-outer: 8 LDS + 16 FMA per feature)
    const float* mx = sx + tid * XS;
    float d[16];
    #pragma unroll
    for (int i = 0; i < 16; i++) d[i] = 0.f;
    #pragma unroll
    for (int f = 0; f < 14; f++) {
        float x0 = mx[f], x1 = mx[14+f], x2 = mx[28+f], x3 = mx[42+f];
        float t0 = sT[f], t1 = sT[14+f], t2 = sT[28+f], t3 = sT[42+f];
        d[0]  += x0*t0; d[1]  += x0*t1; d[2]  += x0*t2; d[3]  += x0*t3;
        d[4]  += x1*t0; d[5]  += x1*t1; d[6]  += x1*t2; d[7]  += x1*t3;
        d[8]  += x2*t0; d[9]  += x2*t1; d[10] += x2*t2; d[11] += x2*t3;
        d[12] += x3*t0; d[13] += x3*t1; d[14] += x3*t2; d[15] += x3*t3;
    }
    float acc = sT[60] + R[0]*sT[56] + R[1]*sT[57] + R[2]*sT[58] + R[3]*sT[59];
    #pragma unroll
    for (int n = 0; n < 4; n++)
        #pragma unroll
        for (int p = 0; p < 4; p++)
            acc += A2[n*4+p] * d[p*4+n];

    out[blockIdx.x * TPB + tid] = acc;
}

extern "C" void kernel_launch(void* const* d_in, const int* in_sizes, int n_in,
                              void* d_out, int out_size)
{
    const float* x   = (const float*)d_in[0];
    const int*   ei  = (const int*)  d_in[1];
    const float* W1  = (const float*)d_in[2];
    const float* b1  = (const float*)d_in[3];
    const float* W2  = (const float*)d_in[4];
    const float* b2  = (const float*)d_in[5];
    const float* Wl1 = (const float*)d_in[6];
    const float* bl1 = (const float*)d_in[7];
    const float* Wl2 = (const float*)d_in[8];
    const float* bl2 = (const float*)d_in[9];
    const float* Wl3 = (const float*)d_in[10];
    const float* bl3 = (const float*)d_in[11];
    const float* wl4 = (const float*)d_in[12];
    const float* bl4 = (const float*)d_in[13];

    int B = in_sizes[0] / 56;   // 262144

    matvec256<<<32, 256>>>(Wl3, wl4, nullptr, 0);  // g_p1 = Wl3.wl4
    matvec256<<<32, 256>>>(Wl2, nullptr, wl4, 1);  // g_q  = Wl2.p1 + wl4
    matvec256<<<32, 256>>>(Wl1, nullptr, wl4, 2);  // g_M  = Wl1.q  + wl4
    finalize<<<1, 256>>>(W1, b1, W2, b2, bl1, bl2, bl3, wl4, bl4);
    gcn_main<<<B / TPB, TPB>>>(x, ei, (float*)d_out);
}

// round 5
// speedup vs baseline: 2.4391x; 1.0094x over previous
#include <cuda_runtime.h>
#include <cstdint>

// ---------------------------------------------------------------------------
// out[b] = sum_{n,p} (Agg_b^2)[n,p] * (x_b[p] . t_n)
//        + sum_n rowsum(Agg_b)[n] * s_n  +  c1
//
// Precompute (all row-pattern matvecs):
//   p1 = Wl3 . wl4
//   q  = Wl2 . p1 + wl4
//   M  = Wl1 . q  + wl4
//   c0 = bl1.q + bl2.p1 + bl3.wl4 + bl4
//   v_n = W2 @ M_n ; t_n = W1 @ v_n ; s_n = b1.v_n ; c1 = c0 + sum_n b2.M_n
// ---------------------------------------------------------------------------

__device__ float g_p1[256];
__device__ float g_q[256];
__device__ float g_M[256];
__device__ float g_TSC[61];   // T[56], s[4], c1

// ---- warp-per-row 256x256 matvec; globals selected BY SYMBOL in device code
__global__ void matvec256(const float* __restrict__ W, const float* __restrict__ extv,
                          const float* __restrict__ addv, int stage)
{
    const float* v = (stage == 0) ? extv : (stage == 1 ? g_p1 : g_q);
    float* outv    = (stage == 0) ? g_p1 : (stage == 1 ? g_q  : g_M);
    int warp = threadIdx.x >> 5, lane = threadIdx.x & 31;
    int r = blockIdx.x * 8 + warp;
    const float* row = W + (size_t)r * 256;
    float a = 0.f;
    #pragma unroll
    for (int k = 0; k < 8; k++) a += row[lane + 32 * k] * v[lane + 32 * k];
    #pragma unroll
    for (int o = 16; o > 0; o >>= 1) a += __shfl_xor_sync(0xFFFFFFFFu, a, o);
    if (lane == 0) outv[r] = a + (addv ? addv[r] : 0.f);
}

// ---- finalize: latency-optimized single block, 512 threads
__global__ __launch_bounds__(512)
void finalize(const float* __restrict__ W1, const float* __restrict__ b1,
              const float* __restrict__ W2, const float* __restrict__ b2,
              const float* __restrict__ bl1, const float* __restrict__ bl2,
              const float* __restrict__ bl3, const float* __restrict__ wl4,
              const float* __restrict__ bl4)
{
    __shared__ float sM[256];
    __shared__ float sV[512];
    __shared__ float sRed[16];
    int t = threadIdx.x;
    int wid = t >> 5, lane = t & 31;

    // V-output index: o = t in [0,512): n = o>>7, k = o&127
    int n = t >> 7, k = t & 127;

    // Issue W2 row loads immediately (16 independent LDG.128)
    float4 w[16];
    const float4* w4 = (const float4*)(W2 + (size_t)k * 64);
    #pragma unroll
    for (int j = 0; j < 16; j++) w[j] = w4[j];

    float contrib = 0.f;
    if (t < 256) {
        sM[t] = g_M[t];
        contrib = bl1[t] * g_q[t] + bl2[t] * g_p1[t] + bl3[t] * wl4[t];
    }
    __syncthreads();
    if (t < 64)
        contrib += b2[t] * (sM[t] + sM[64 + t] + sM[128 + t] + sM[192 + t]);
    // warp-level reduce of contrib, then 16-entry shared stage
    #pragma unroll
    for (int o = 16; o > 0; o >>= 1) contrib += __shfl_xor_sync(0xFFFFFFFFu, contrib, o);
    if (lane == 0) sRed[wid] = contrib;

    // V[o] = W2[k,:] . M_n
    {
        const float4* m4 = (const float4*)(sM + n * 64);
        float a = 0.f;
        #pragma unroll
        for (int j = 0; j < 16; j++) {
            float4 mm = m4[j];
            a += w[j].x * mm.x + w[j].y * mm.y + w[j].z * mm.z + w[j].w * mm.w;
        }
        sV[t] = a;
    }
    __syncthreads();

    // T/s/c1: warp-per-row, rows r = wid*4 + rep (0..63); 60 real rows + c1
    float4 wr[4];
    int rows[4];
    #pragma unroll
    for (int rep = 0; rep < 4; rep++) {
        int r = wid * 4 + rep;
        rows[rep] = r;
        if (r < 56) {
            int i = r % 14;
            wr[rep] = ((const float4*)(W1 + (size_t)i * 128))[lane];
        } else if (r < 60) {
            wr[rep] = ((const float4*)b1)[lane];
        } else {
            wr[rep] = make_float4(0.f, 0.f, 0.f, 0.f);
        }
    }
    #pragma unroll
    for (int rep = 0; rep < 4; rep++) {
        int r = rows[rep];
        if (r < 60) {
            int nn = (r < 56) ? (r / 14) : (r - 56);
            float4 vv = ((const float4*)(sV + nn * 128))[lane];
            float a = wr[rep].x * vv.x + wr[rep].y * vv.y
                    + wr[rep].z * vv.z + wr[rep].w * vv.w;
            #pragma unroll
            for (int o = 16; o > 0; o >>= 1) a += __shfl_xor_sync(0xFFFFFFFFu, a, o);
            if (lane == 0) g_TSC[r] = a;
        } else if (r == 60 && lane == 0) {
            float c = bl4[0];
            #pragma unroll
            for (int j = 0; j < 16; j++) c += sRed[j];
            g_TSC[60] = c;
        }
    }
}

// ---- main kernel: 128 threads/block, static shared (no opt-in attribute)
#define TPB 128
#define XS 57
#define ES 25

__global__ __launch_bounds__(TPB)
void gcn_main(const float* __restrict__ x, const int* __restrict__ eidx,
              float* __restrict__ out)
{
    __shared__ float sx[TPB * XS];
    __shared__ int   se[TPB * ES];
    __shared__ float sT[64];
    int tid = threadIdx.x;

    // ---- stage: fully coalesced global -> shared (all 20 loads in flight)
    const float4* Xg = (const float4*)x + (size_t)blockIdx.x * TPB * 14;
    const int4*   Eg = (const int4*)eidx + (size_t)blockIdx.x * TPB * 6;
    float4 xv[14];
    int4   ev[6];
    #pragma unroll
    for (int i = 0; i < 14; i++) xv[i] = Xg[i * TPB + tid];
    #pragma unroll
    for (int i = 0; i < 6; i++)  ev[i] = Eg[i * TPB + tid];
    if (tid < 61) sT[tid] = g_TSC[tid];
    #pragma unroll
    for (int i = 0; i < 14; i++) {
        int idx4 = i * TPB + tid;          // float4 index in block tile
        int s = idx4 / 14, j = idx4 % 14;  // sample, float4-within-sample
        float* dst = sx + s * XS + j * 4;
        dst[0] = xv[i].x; dst[1] = xv[i].y; dst[2] = xv[i].z; dst[3] = xv[i].w;
    }
    #pragma unroll
    for (int i = 0; i < 6; i++) {
        int i4 = i * TPB + tid;
        int s = i4 / 6, r = i4 % 6;
        int* dst = se + s * ES + r * 4;
        dst[0] = ev[i].x; dst[1] = ev[i].y; dst[2] = ev[i].z; dst[3] = ev[i].w;
    }
    __syncthreads();

    // ---- per-sample graph math (odd LDS strides -> conflict-free)
    const int* me = se + tid * ES;
    unsigned h0 = 1u + (1u << 20);         // self loops: codes 0, 5
    unsigned h1 = (1u << 8) + (1u << 28);  // codes 10, 15
    #pragma unroll
    for (int e = 0; e < 12; e++) {
        int code = (me[12 + e] << 2) | me[e];   // dst*4 + src
        unsigned inc = 1u << ((code & 7) << 2);
        if (code & 8) h1 += inc; else h0 += inc;
    }
    float c[16];
    #pragma unroll
    for (int qd = 0; qd < 8; qd++) {
        c[qd]     = (float)((h0 >> (qd * 4)) & 15u);
        c[qd + 8] = (float)((h1 >> (qd * 4)) & 15u);
    }
    float dinv[4];
    #pragma unroll
    for (int d = 0; d < 4; d++)
        dinv[d] = rsqrtf(c[4*d] + c[4*d+1] + c[4*d+2] + c[4*d+3]);
    float A[16];
    #pragma unroll
    for (int d = 0; d < 4; d++)
        #pragma unroll
        for (int s = 0; s < 4; s++)
            A[d*4+s] = c[d*4+s] * dinv[d] * dinv[s];
    float A2[16], R[4];
    #pragma unroll
    for (int n = 0; n < 4; n++) {
        R[n] = A[n*4] + A[n*4+1] + A[n*4+2] + A[n*4+3];
        #pragma unroll
        for (int p = 0; p < 4; p++) {
            A2[n*4+p] = A[n*4+0] * A[0*4+p] + A[n*4+1] * A[1*4+p]
                      + A[n*4+2] * A[2*4+p] + A[n*4+3] * A[3*4+p];
        }
    }

    // d[p*4+n] = x_p . t_n   (f-outer: 8 LDS + 16 FMA per feature)
    const float* mx = sx + tid * XS;
    float d[16];
    #pragma unroll
    for (int i = 0; i < 16; i++) d[i] = 0.f;
    #pragma unroll
    for (int f = 0; f < 14; f++) {
        float x0 = mx[f], x1 = mx[14+f], x2 = mx[28+f], x3 = mx[42+f];
        float t0 = sT[f], t1 = sT[14+f], t2 = sT[28+f], t3 = sT[42+f];
        d[0]  += x0*t0; d[1]  += x0*t1; d[2]  += x0*t2; d[3]  += x0*t3;
        d[4]  += x1*t0; d[5]  += x1*t1; d[6]  += x1*t2; d[7]  += x1*t3;
        d[8]  += x2*t0; d[9]  += x2*t1; d[10] += x2*t2; d[11] += x2*t3;
        d[12] += x3*t0; d[13] += x3*t1; d[14] += x3*t2; d[15] += x3*t3;
    }
    float acc = sT[60] + R[0]*sT[56] + R[1]*sT[57] + R[2]*sT[58] + R[3]*sT[59];
    #pragma unroll
    for (int n = 0; n < 4; n++)
        #pragma unroll
        for (int p = 0; p < 4; p++)
            acc += A2[n*4+p] * d[p*4+n];

    out[blockIdx.x * TPB + tid] = acc;
}

extern "C" void kernel_launch(void* const* d_in, const int* in_sizes, int n_in,
                              void* d_out, int out_size)
{
    const float* x   = (const float*)d_in[0];
    const int*   ei  = (const int*)  d_in[1];
    const float* W1  = (const float*)d_in[2];
    const float* b1  = (const float*)d_in[3];
    const float* W2  = (const float*)d_in[4];
    const float* b2  = (const float*)d_in[5];
    const float* Wl1 = (const float*)d_in[6];
    const float* bl1 = (const float*)d_in[7];
    const float* Wl2 = (const float*)d_in[8];
    const float* bl2 = (const float*)d_in[9];
    const float* Wl3 = (const float*)d_in[10];
    const float* bl3 = (const float*)d_in[11];
    const float* wl4 = (const float*)d_in[12];
    const float* bl4 = (const float*)d_in[13];

    int B = in_sizes[0] / 56;   // 262144

    matvec256<<<32, 256>>>(Wl3, wl4, nullptr, 0);  // g_p1 = Wl3.wl4
    matvec256<<<32, 256>>>(Wl2, nullptr, wl4, 1);  // g_q  = Wl2.p1 + wl4
    matvec256<<<32, 256>>>(Wl1, nullptr, wl4, 2);  // g_M  = Wl1.q  + wl4
    finalize<<<1, 512>>>(W1, b1, W2, b2, bl1, bl2, bl3, wl4, bl4);
    gcn_main<<<B / TPB, TPB>>>(x, ei, (float*)d_out);
}